// round 16
// baseline (speedup 1.0000x reference)
#include <cuda_runtime.h>
#include <cuda_bf16.h>
#include <cstdint>

#define NB   16
#define NPTS 16384
#define NCH  288
#define NS   256
#define NKS  16
#define MTOT (NB*NS*NKS)   /* 65536 rows */
#define LDK  288           /* K for all layers (xyz handled in epilogue) */
#define R2   0.09f
#define FCNB 8             /* FPS cluster size (CTAs per batch) */
#define FTHR 256
#define FPPT 8             /* points per thread: 16384/8/256 */

// ---------------- scratch (device globals, zero-initialized) ------------------
__device__ int g_ballidx[NB*NS*NKS];
__device__ float g_xyzr[(size_t)MTOT*3];
__device__ __align__(16) __nv_bfloat16 g_X0h[(size_t)MTOT*LDK];
__device__ __align__(16) __nv_bfloat16 g_X0l[(size_t)MTOT*LDK];
__device__ __align__(16) __nv_bfloat16 g_X1h[(size_t)MTOT*LDK];
__device__ __align__(16) __nv_bfloat16 g_X1l[(size_t)MTOT*LDK];
__device__ __align__(16) __nv_bfloat16 g_X2h[(size_t)MTOT*LDK];
__device__ __align__(16) __nv_bfloat16 g_X2l[(size_t)MTOT*LDK];
__device__ __align__(16) __nv_bfloat16 g_W0h[NCH*LDK];
__device__ __align__(16) __nv_bfloat16 g_W0l[NCH*LDK];
__device__ __align__(16) __nv_bfloat16 g_W1h[NCH*LDK];
__device__ __align__(16) __nv_bfloat16 g_W1l[NCH*LDK];
__device__ __align__(16) __nv_bfloat16 g_W2h[NCH*LDK];
__device__ __align__(16) __nv_bfloat16 g_W2l[NCH*LDK];

// single dynamic-smem symbol for the whole TU (gemm only)
extern __shared__ char dynsm[];

// ---------------- helpers -----------------------------------------------------
__device__ __forceinline__ void cp16(uint32_t dst, const void* src){
    asm volatile("cp.async.cg.shared.global [%0], [%1], 16;" :: "r"(dst), "l"(src));
}
__device__ __forceinline__ void cp_commit(){
    asm volatile("cp.async.commit_group;");
}
template<int N> __device__ __forceinline__ void cp_wait(){
    asm volatile("cp.async.wait_group %0;" :: "n"(N));
}
__device__ __forceinline__ void ldm_x4(uint32_t* r, uint32_t addr){
    asm volatile("ldmatrix.sync.aligned.m8n8.x4.shared.b16 {%0,%1,%2,%3}, [%4];"
        : "=r"(r[0]), "=r"(r[1]), "=r"(r[2]), "=r"(r[3]) : "r"(addr));
}
__device__ __forceinline__ void mma_bf16(float* c, const uint32_t* a,
                                         uint32_t b0, uint32_t b1){
    asm volatile("mma.sync.aligned.m16n8k16.row.col.f32.bf16.bf16.f32 "
        "{%0,%1,%2,%3}, {%4,%5,%6,%7}, {%8,%9}, {%0,%1,%2,%3};"
        : "+f"(c[0]), "+f"(c[1]), "+f"(c[2]), "+f"(c[3])
        : "r"(a[0]), "r"(a[1]), "r"(a[2]), "r"(a[3]), "r"(b0), "r"(b1));
}
__device__ __forceinline__ void split_hl(float v, __nv_bfloat16& h, __nv_bfloat16& l){
    h = __float2bfloat16(v);
    l = __float2bfloat16(v - __bfloat162float(h));
}

// ---------------- FPS: 8-CTA cluster per batch, DSMEM mailbox -----------------
__global__ void __launch_bounds__(FTHR,1) __cluster_dims__(FCNB,1,1)
fps_kernel(const float* __restrict__ xyz, float* __restrict__ o_xyz,
           float* __restrict__ o_inds)
{
    int bb  = blockIdx.x;          // 0..127
    int b   = bb >> 3;             // batch  (cluster id)
    int blk = bb & (FCNB-1);       // rank within cluster
    int t   = threadIdx.x;
    int wid = t >> 5, lane = t & 31;

    __shared__ __align__(16) float s_mb[2][4];   // mailbox: v,x,y,z per parity
    __shared__ int   s_mbi[2];
    __shared__ float s_v[8], s_x[8], s_y[8], s_z[8];
    __shared__ int   s_i[8];

    uint32_t mb_a  = (uint32_t)__cvta_generic_to_shared(&s_mb[0][0]);
    uint32_t mbi_a = (uint32_t)__cvta_generic_to_shared(&s_mbi[0]);

    const float* base = xyz + (size_t)b*NPTS*3;
    int p0 = blk*(NPTS/FCNB) + t*FPPT;

    float px[FPPT], py[FPPT], pz[FPPT], dist[FPPT];
    #pragma unroll
    for (int i = 0; i < FPPT; i++) {
        px[i] = base[3*(p0+i)]; py[i] = base[3*(p0+i)+1]; pz[i] = base[3*(p0+i)+2];
        dist[i] = 1e10f;
    }

    float cx = base[0], cy = base[1], cz = base[2];
    int curi = 0;

    for (int k = 0; k < NS; k++) {
        if (blk == 0 && t == 0) {
            o_inds[b*NS + k] = (float)curi;
            o_xyz[(b*NS + k)*3 + 0] = cx;
            o_xyz[(b*NS + k)*3 + 1] = cy;
            o_xyz[(b*NS + k)*3 + 2] = cz;
        }
        float bv = -1.0f, bx = 0.f, by = 0.f, bz = 0.f; int bi = 0x3FFFFFFF;
        #pragma unroll
        for (int i = 0; i < FPPT; i++) {
            float dx = px[i]-cx, dy = py[i]-cy, dz = pz[i]-cz;
            // exact XLA order: (dx*dx + dy*dy) + dz*dz, no fma contraction
            float d = __fadd_rn(__fadd_rn(__fmul_rn(dx,dx),__fmul_rn(dy,dy)),
                                __fmul_rn(dz,dz));
            float nd = fminf(dist[i], d);
            dist[i] = nd;
            if (nd > bv) { bv = nd; bi = p0+i; bx = px[i]; by = py[i]; bz = pz[i]; }
        }
        // warp reduce (val,idx,x,y,z), tie -> lower idx
        #pragma unroll
        for (int o = 16; o > 0; o >>= 1) {
            float ov = __shfl_down_sync(0xffffffffu, bv, o);
            int   oi = __shfl_down_sync(0xffffffffu, bi, o);
            float ox = __shfl_down_sync(0xffffffffu, bx, o);
            float oy = __shfl_down_sync(0xffffffffu, by, o);
            float oz = __shfl_down_sync(0xffffffffu, bz, o);
            if (ov > bv || (ov == bv && oi < bi)) { bv=ov; bi=oi; bx=ox; by=oy; bz=oz; }
        }
        if (lane == 0) { s_v[wid]=bv; s_i[wid]=bi; s_x[wid]=bx; s_y[wid]=by; s_z[wid]=bz; }
        __syncthreads();

        int par = k & 1;
        if (wid == 0) {
            bv = (lane < 8) ? s_v[lane] : -1.0f;
            bi = (lane < 8) ? s_i[lane] : 0x3FFFFFFF;
            bx = (lane < 8) ? s_x[lane] : 0.f;
            by = (lane < 8) ? s_y[lane] : 0.f;
            bz = (lane < 8) ? s_z[lane] : 0.f;
            #pragma unroll
            for (int o = 4; o > 0; o >>= 1) {
                float ov = __shfl_down_sync(0xffffffffu, bv, o);
                int   oi = __shfl_down_sync(0xffffffffu, bi, o);
                float ox = __shfl_down_sync(0xffffffffu, bx, o);
                float oy = __shfl_down_sync(0xffffffffu, by, o);
                float oz = __shfl_down_sync(0xffffffffu, bz, o);
                if (ov > bv || (ov == bv && oi < bi)) { bv=ov; bi=oi; bx=ox; by=oy; bz=oz; }
            }
            if (lane == 0) {
                s_mb[par][0]=bv; s_mb[par][1]=bx; s_mb[par][2]=by; s_mb[par][3]=bz;
                s_mbi[par]=bi;
            }
        }
        // cluster barrier: arrive(release) orders the mailbox store; wait = acquire
        asm volatile("barrier.cluster.arrive.aligned;" ::: "memory");
        asm volatile("barrier.cluster.wait.aligned;" ::: "memory");

        // EVERY warp reads the 8 mailboxes and combines (no extra __syncthreads)
        {
            float vj = -1.0f, xj = 0.f, yj = 0.f, zj = 0.f; int ij = 0x3FFFFFFF;
            if (lane < FCNB) {
                uint32_t pa, pai;
                asm("mapa.shared::cluster.u32 %0, %1, %2;"
                    : "=r"(pa) : "r"(mb_a + (uint32_t)par*16), "r"(lane));
                asm("mapa.shared::cluster.u32 %0, %1, %2;"
                    : "=r"(pai) : "r"(mbi_a + (uint32_t)par*4), "r"(lane));
                asm volatile("ld.shared::cluster.v4.f32 {%0,%1,%2,%3}, [%4];"
                    : "=f"(vj), "=f"(xj), "=f"(yj), "=f"(zj) : "r"(pa));
                asm volatile("ld.shared::cluster.s32 %0, [%1];"
                    : "=r"(ij) : "r"(pai));
            }
            #pragma unroll
            for (int o = 4; o > 0; o >>= 1) {
                float ov = __shfl_down_sync(0xffffffffu, vj, o);
                int   oi = __shfl_down_sync(0xffffffffu, ij, o);
                float ox = __shfl_down_sync(0xffffffffu, xj, o);
                float oy = __shfl_down_sync(0xffffffffu, yj, o);
                float oz = __shfl_down_sync(0xffffffffu, zj, o);
                if (ov > vj || (ov == vj && oi < ij)) { vj=ov; ij=oi; xj=ox; yj=oy; zj=oz; }
            }
            cx   = __shfl_sync(0xffffffffu, xj, 0);
            cy   = __shfl_sync(0xffffffffu, yj, 0);
            cz   = __shfl_sync(0xffffffffu, zj, 0);
            curi = __shfl_sync(0xffffffffu, ij, 0);
        }
    }
    // no CTA may exit while peers' DSMEM reads of its smem are in flight
    asm volatile("barrier.cluster.arrive.aligned;" ::: "memory");
    asm volatile("barrier.cluster.wait.aligned;" ::: "memory");
}

// ---------------- ball query: one warp per center ----------------------------
__global__ void ball_kernel(const float* __restrict__ xyz,
                            const float* __restrict__ nxyz,
                            int* __restrict__ bidx)
{
    int gw = (blockIdx.x*blockDim.x + threadIdx.x) >> 5;
    int lane = threadIdx.x & 31;
    if (gw >= NB*NS) return;
    int b = gw >> 8;
    const float* px = xyz + (size_t)b*NPTS*3;
    float cx = nxyz[gw*3], cy = nxyz[gw*3+1], cz = nxyz[gw*3+2];
    int cnt = 0, first = -1;
    for (int n0 = 0; n0 < NPTS; n0 += 32) {
        int n = n0 + lane;
        float dx = px[3*n]-cx, dy = px[3*n+1]-cy, dz = px[3*n+2]-cz;
        float d2 = __fadd_rn(__fadd_rn(__fmul_rn(dx,dx),__fmul_rn(dy,dy)),
                             __fmul_rn(dz,dz));
        bool in = d2 < R2;
        unsigned m = __ballot_sync(0xffffffffu, in);
        if (first < 0 && m) first = n0 + __ffs(m) - 1;
        int pos = cnt + __popc(m & ((1u << lane) - 1u));
        if (in && pos < NKS) bidx[gw*NKS + pos] = n;
        cnt += __popc(m);
        if (cnt >= NKS) break;
    }
    int c = cnt < NKS ? cnt : NKS;
    for (int p = c + lane; p < NKS; p += 32) bidx[gw*NKS + p] = first;
}

// ---------------- gather (features + fp32 xyz rows) + W pack ------------------
// blocks [0, 4096): gather (2 y-halves x 8 samples);  [4096, +3*NCH): W pack
__global__ void __launch_bounds__(576)
gatherpack_kernel(const float* __restrict__ xyz,
                  const float* __restrict__ feat,
                  const float* __restrict__ nxyz,
                  const int* __restrict__ bidx,
                  __nv_bfloat16* __restrict__ Xh, __nv_bfloat16* __restrict__ Xl,
                  float* __restrict__ xyzr,
                  const float* __restrict__ W0, const float* __restrict__ W1,
                  const float* __restrict__ W2,
                  __nv_bfloat16* __restrict__ W0h, __nv_bfloat16* __restrict__ W0l,
                  __nv_bfloat16* __restrict__ W1h, __nv_bfloat16* __restrict__ W1l,
                  __nv_bfloat16* __restrict__ W2h, __nv_bfloat16* __restrict__ W2l)
{
    int w = blockIdx.x;
    int t = threadIdx.x;
    int ty = threadIdx.y;

    if (w >= NB*NS) {
        if (ty) return;
        int r = w - NB*NS;                 // 0 .. 3*NCH-1
        int L = r / NCH, o = r % NCH;
        __nv_bfloat16 h, l;
        if (L == 0)      split_hl(W0[o*291 + 3 + t], h, l);   // feature cols only
        else if (L == 1) split_hl(W1[o*288 + t], h, l);
        else             split_hl(W2[o*288 + t], h, l);
        __nv_bfloat16* Wh = (L == 0) ? W0h : (L == 1) ? W1h : W2h;
        __nv_bfloat16* Wl = (L == 0) ? W0l : (L == 1) ? W1l : W2l;
        Wh[o*LDK + t] = h; Wl[o*LDK + t] = l;
        return;
    }

    int b = w >> 8;
    int j0 = ty * 8;
    int n[8];
    #pragma unroll
    for (int j = 0; j < 8; j++) n[j] = bidx[w*NKS + j0 + j];

    const float* frow = feat + (size_t)(b*NCH + t)*NPTS;
    #pragma unroll
    for (int j = 0; j < 8; j++) {
        size_t row = (size_t)(w*NKS + j0 + j);
        __nv_bfloat16 h, l;
        split_hl(frow[n[j]], h, l);
        Xh[row*LDK + t] = h; Xl[row*LDK + t] = l;
        if (t < 3) {
            float p = xyz[((size_t)b*NPTS + n[j])*3 + t];
            float c = nxyz[w*3 + t];
            xyzr[row*3 + t] = __fdiv_rn(p - c, 0.3f);
        }
    }
}

// ---------------- mma.sync bf16-split GEMM + BN + ReLU (+xyz / +maxpool) ------
// CTA tile 128(M) x 96(N), K-chunk 32 (NC=9), 3-stage cp.async (2 CTAs/SM)
// single barrier per chunk: wait -> sync -> prefetch c+2 -> compute c
#define A_PL 8192               /* 128 rows * 64B */
#define B_PL 6144               /* 96 rows * 64B */
#define STG  (2*A_PL + 2*B_PL)  /* 28672 */
#define NSTG 3
#define NC   9

template<int MODE, int XYZ>   // MODE 0: write hi/lo planes of next X   1: fused maxpool
__global__ void __launch_bounds__(256,2)
gemm_mma(const __nv_bfloat16* __restrict__ Ah_g, const __nv_bfloat16* __restrict__ Al_g,
         const __nv_bfloat16* __restrict__ Wh_g, const __nv_bfloat16* __restrict__ Wl_g,
         const float* __restrict__ gg, const float* __restrict__ bb,
         const float* __restrict__ mmn, const float* __restrict__ vv,
         const float* __restrict__ w0raw, const float* __restrict__ xyzr,
         __nv_bfloat16* __restrict__ Xh_n, __nv_bfloat16* __restrict__ Xl_n,
         float* __restrict__ ofeat)
{
    __shared__ float s_sc[96], s_mu[96], s_be[96];
    __shared__ float s_w3[96*3];
    char* sm = dynsm;
    uint32_t smb = (uint32_t)__cvta_generic_to_shared(sm);

    int tid = threadIdx.x, lane = tid & 31, warp = tid >> 5;
    int brow = blockIdx.x * 128;
    int bcol = blockIdx.y * 96;
    int m_base = (warp >> 1) * 32;
    int n_base = (warp & 1) * 48;

    auto stage_load = [&](int c, int buf){
        int kc = c * 32;
        uint32_t sb = smb + buf*STG;
        #pragma unroll
        for (int i = 0; i < 4; i++) {
            int idx = tid + i*256;
            int plane = idx >> 9, rem = idx & 511;
            int r = rem >> 2, ch = rem & 3;
            uint32_t d = sb + plane*A_PL + r*64 + ((ch ^ (r & 3)) << 4);
            size_t gs = (size_t)(brow + r)*LDK + kc + ch*8;
            cp16(d, (plane ? Al_g : Ah_g) + gs);
        }
        #pragma unroll
        for (int i = 0; i < 3; i++) {
            int idx = tid + i*256;
            int plane = (idx >= 384), rem = plane ? idx - 384 : idx;
            int r = rem >> 2, ch = rem & 3;
            uint32_t d = sb + 2*A_PL + plane*B_PL + r*64 + ((ch ^ (r & 3)) << 4);
            size_t gs = (size_t)(bcol + r)*LDK + kc + ch*8;
            cp16(d, (plane ? Wl_g : Wh_g) + gs);
        }
    };

    stage_load(0, 0); cp_commit();
    stage_load(1, 1); cp_commit();

    for (int t = tid; t < 96; t += 256) {
        int gc = bcol + t;
        s_sc[t] = gg[gc] * rsqrtf(vv[gc] + 1e-5f);
        s_mu[t] = mmn[gc]; s_be[t] = bb[gc];
    }
    if (XYZ) {
        for (int u = tid; u < 288; u += 256) {
            int cc = u / 3, c = u % 3;
            s_w3[u] = w0raw[(size_t)(bcol + cc)*291 + c];
        }
    }

    float C[2][6][4];
    #pragma unroll
    for (int tm = 0; tm < 2; tm++)
        #pragma unroll
        for (int j = 0; j < 6; j++)
            #pragma unroll
            for (int e = 0; e < 4; e++) C[tm][j][e] = 0.f;

    int rA = (lane & 7) + ((lane & 8) ? 8 : 0);
    int chSelA = lane >> 4;
    int rB = (lane & 7) + ((lane & 16) ? 8 : 0);
    int chSelB = (lane >> 3) & 1;

    for (int c = 0; c < NC; c++) {
        int buf = c % NSTG;
        if (c + 1 < NC) cp_wait<1>(); else cp_wait<0>();
        __syncthreads();
        if (c + 2 < NC) { stage_load(c + 2, (c + 2) % NSTG); cp_commit(); }

        uint32_t sb = smb + buf*STG;
        uint32_t aH = sb, aL = sb + A_PL;
        uint32_t bH = sb + 2*A_PL, bL = bH + B_PL;

        #pragma unroll
        for (int ks = 0; ks < 2; ks++) {
            uint32_t ah[2][4], al[2][4];
            #pragma unroll
            for (int tm = 0; tm < 2; tm++) {
                int r = m_base + tm*16 + rA;
                int ch = ks*2 + chSelA;
                uint32_t off = r*64 + ((ch ^ (r & 3)) << 4);
                ldm_x4(ah[tm], aH + off);
                ldm_x4(al[tm], aL + off);
            }
            uint32_t bh[3][4], bl[3][4];
            #pragma unroll
            for (int jp = 0; jp < 3; jp++) {
                int r = n_base + jp*16 + rB;
                int ch = ks*2 + chSelB;
                uint32_t off = r*64 + ((ch ^ (r & 3)) << 4);
                ldm_x4(bh[jp], bH + off);
                ldm_x4(bl[jp], bL + off);
            }
            #pragma unroll
            for (int tm = 0; tm < 2; tm++)
                #pragma unroll
                for (int jp = 0; jp < 3; jp++) {
                    mma_bf16(C[tm][2*jp],   ah[tm], bh[jp][0], bh[jp][1]);
                    mma_bf16(C[tm][2*jp],   ah[tm], bl[jp][0], bl[jp][1]);
                    mma_bf16(C[tm][2*jp],   al[tm], bh[jp][0], bh[jp][1]);
                    mma_bf16(C[tm][2*jp+1], ah[tm], bh[jp][2], bh[jp][3]);
                    mma_bf16(C[tm][2*jp+1], ah[tm], bl[jp][2], bl[jp][3]);
                    mma_bf16(C[tm][2*jp+1], al[tm], bh[jp][2], bh[jp][3]);
                }
        }
    }

    // ---------------- epilogue ----------------
    int tq = lane >> 2, tr = lane & 3;
    float xr[4][3];
    if (XYZ) {
        #pragma unroll
        for (int q = 0; q < 4; q++) {
            int rr = brow + m_base + (q >> 1)*16 + (q & 1)*8 + tq;
            xr[q][0] = xyzr[(size_t)rr*3 + 0];
            xr[q][1] = xyzr[(size_t)rr*3 + 1];
            xr[q][2] = xyzr[(size_t)rr*3 + 2];
        }
    }
    #pragma unroll
    for (int tm = 0; tm < 2; tm++) {
        #pragma unroll
        for (int j = 0; j < 6; j++) {
            int lc = n_base + j*8 + tr*2;
            int col = bcol + lc;
            float c0 = C[tm][j][0], c1 = C[tm][j][1];
            float c2 = C[tm][j][2], c3 = C[tm][j][3];
            if (XYZ) {
                const float* wa = &s_w3[lc*3];
                const float* wb = &s_w3[(lc+1)*3];
                int qa = tm*2, qb = tm*2 + 1;
                c0 += xr[qa][0]*wa[0] + xr[qa][1]*wa[1] + xr[qa][2]*wa[2];
                c1 += xr[qa][0]*wb[0] + xr[qa][1]*wb[1] + xr[qa][2]*wb[2];
                c2 += xr[qb][0]*wa[0] + xr[qb][1]*wa[1] + xr[qb][2]*wa[2];
                c3 += xr[qb][0]*wb[0] + xr[qb][1]*wb[1] + xr[qb][2]*wb[2];
            }
            float y0 = fmaxf(__fmaf_rn(c0 - s_mu[lc],   s_sc[lc],   s_be[lc]),   0.f);
            float y1 = fmaxf(__fmaf_rn(c1 - s_mu[lc+1], s_sc[lc+1], s_be[lc+1]), 0.f);
            float y2 = fmaxf(__fmaf_rn(c2 - s_mu[lc],   s_sc[lc],   s_be[lc]),   0.f);
            float y3 = fmaxf(__fmaf_rn(c3 - s_mu[lc+1], s_sc[lc+1], s_be[lc+1]), 0.f);

            if (MODE == 0) {
                size_t r0 = (size_t)(brow + m_base + tm*16 + tq)*LDK + col;
                size_t r1 = r0 + 8*LDK;
                __nv_bfloat16 h0,l0,h1,l1;
                split_hl(y0,h0,l0); split_hl(y1,h1,l1);
                *(__nv_bfloat162*)(Xh_n + r0) = __nv_bfloat162(h0,h1);
                *(__nv_bfloat162*)(Xl_n + r0) = __nv_bfloat162(l0,l1);
                split_hl(y2,h0,l0); split_hl(y3,h1,l1);
                *(__nv_bfloat162*)(Xh_n + r1) = __nv_bfloat162(h0,h1);
                *(__nv_bfloat162*)(Xl_n + r1) = __nv_bfloat162(l0,l1);
            } else {
                float m0 = fmaxf(y0, y2), m1 = fmaxf(y1, y3);
                #pragma unroll
                for (int o = 4; o <= 16; o <<= 1) {
                    m0 = fmaxf(m0, __shfl_xor_sync(0xffffffffu, m0, o));
                    m1 = fmaxf(m1, __shfl_xor_sync(0xffffffffu, m1, o));
                }
                if (tq == 0) {
                    int center = (brow + m_base + tm*16) >> 4;
                    int b = center >> 8, s = center & 255;
                    ofeat[((size_t)b*NCH + col)*NS + s]     = m0;
                    ofeat[((size_t)b*NCH + col+1)*NS + s]   = m1;
                }
            }
        }
    }
}

// ---------------- launch ------------------------------------------------------
extern "C" void kernel_launch(void* const* d_in, const int* in_sizes, int n_in,
                              void* d_out, int out_size)
{
    const float* xyz  = (const float*)d_in[0];
    const float* feat = (const float*)d_in[1];
    const float* W0 = (const float*)d_in[2];
    const float* g0 = (const float*)d_in[3];
    const float* b0 = (const float*)d_in[4];
    const float* m0 = (const float*)d_in[5];
    const float* v0 = (const float*)d_in[6];
    const float* W1 = (const float*)d_in[7];
    const float* g1 = (const float*)d_in[8];
    const float* b1 = (const float*)d_in[9];
    const float* m1 = (const float*)d_in[10];
    const float* v1 = (const float*)d_in[11];
    const float* W2 = (const float*)d_in[12];
    const float* g2 = (const float*)d_in[13];
    const float* b2 = (const float*)d_in[14];
    const float* m2 = (const float*)d_in[15];
    const float* v2 = (const float*)d_in[16];

    float* out    = (float*)d_out;
    float* o_xyz  = out;
    float* o_feat = out + (size_t)NB*NS*3;
    float* o_inds = o_feat + (size_t)NB*NCH*NS;

    void *pX0h,*pX0l,*pX1h,*pX1l,*pX2h,*pX2l,*pW0h,*pW0l,*pW1h,*pW1l,*pW2h,*pW2l,*pBI,*pXR;
    cudaGetSymbolAddress(&pX0h, g_X0h); cudaGetSymbolAddress(&pX0l, g_X0l);
    cudaGetSymbolAddress(&pX1h, g_X1h); cudaGetSymbolAddress(&pX1l, g_X1l);
    cudaGetSymbolAddress(&pX2h, g_X2h); cudaGetSymbolAddress(&pX2l, g_X2l);
    cudaGetSymbolAddress(&pW0h, g_W0h); cudaGetSymbolAddress(&pW0l, g_W0l);
    cudaGetSymbolAddress(&pW1h, g_W1h); cudaGetSymbolAddress(&pW1l, g_W1l);
    cudaGetSymbolAddress(&pW2h, g_W2h); cudaGetSymbolAddress(&pW2l, g_W2l);
    cudaGetSymbolAddress(&pBI, g_ballidx);
    cudaGetSymbolAddress(&pXR, g_xyzr);

    cudaFuncSetAttribute((gemm_mma<0,1>),
        cudaFuncAttributeMaxDynamicSharedMemorySize, NSTG*STG);
    cudaFuncSetAttribute((gemm_mma<0,0>),
        cudaFuncAttributeMaxDynamicSharedMemorySize, NSTG*STG);
    cudaFuncSetAttribute((gemm_mma<1,0>),
        cudaFuncAttributeMaxDynamicSharedMemorySize, NSTG*STG);

    fps_kernel<<<NB*FCNB, FTHR>>>(xyz, o_xyz, o_inds);
    ball_kernel<<<(NB*NS)/4, 128>>>(xyz, o_xyz, (int*)pBI);
    gatherpack_kernel<<<NB*NS + 3*NCH, dim3(NCH,2)>>>(xyz, feat, o_xyz, (const int*)pBI,
        (__nv_bfloat16*)pX0h, (__nv_bfloat16*)pX0l, (float*)pXR,
        W0, W1, W2,
        (__nv_bfloat16*)pW0h, (__nv_bfloat16*)pW0l,
        (__nv_bfloat16*)pW1h, (__nv_bfloat16*)pW1l,
        (__nv_bfloat16*)pW2h, (__nv_bfloat16*)pW2l);

    dim3 gdim(MTOT/128, 3);
    gemm_mma<0,1><<<gdim, 256, NSTG*STG>>>(
        (const __nv_bfloat16*)pX0h, (const __nv_bfloat16*)pX0l,
        (const __nv_bfloat16*)pW0h, (const __nv_bfloat16*)pW0l,
        g0, b0, m0, v0, W0, (const float*)pXR,
        (__nv_bfloat16*)pX1h, (__nv_bfloat16*)pX1l, nullptr);
    gemm_mma<0,0><<<gdim, 256, NSTG*STG>>>(
        (const __nv_bfloat16*)pX1h, (const __nv_bfloat16*)pX1l,
        (const __nv_bfloat16*)pW1h, (const __nv_bfloat16*)pW1l,
        g1, b1, m1, v1, nullptr, nullptr,
        (__nv_bfloat16*)pX2h, (__nv_bfloat16*)pX2l, nullptr);
    gemm_mma<1,0><<<gdim, 256, NSTG*STG>>>(
        (const __nv_bfloat16*)pX2h, (const __nv_bfloat16*)pX2l,
        (const __nv_bfloat16*)pW2h, (const __nv_bfloat16*)pW2l,
        g2, b2, m2, v2, nullptr, nullptr,
        nullptr, nullptr, o_feat);
}

// round 17
// speedup vs baseline: 1.1224x; 1.1224x over previous
#include <cuda_runtime.h>
#include <cuda_bf16.h>
#include <cstdint>

#define NB   16
#define NPTS 16384
#define NCH  288
#define NS   256
#define NKS  16
#define MTOT (NB*NS*NKS)   /* 65536 rows */
#define LDK  288           /* K for all layers (xyz handled in epilogue) */
#define R2   0.09f
#define FCNB 8             /* FPS cluster size (CTAs per batch) */
#define FTHR 256
#define FPPT 8             /* points per thread: 16384/8/256 */

// ---------------- scratch (device globals, zero-initialized) ------------------
__device__ int g_ballidx[NB*NS*NKS];
__device__ float g_xyzr[(size_t)MTOT*3];
__device__ __align__(16) __nv_bfloat16 g_X0h[(size_t)MTOT*LDK];
__device__ __align__(16) __nv_bfloat16 g_X0l[(size_t)MTOT*LDK];
__device__ __align__(16) __nv_bfloat16 g_X1h[(size_t)MTOT*LDK];
__device__ __align__(16) __nv_bfloat16 g_X1l[(size_t)MTOT*LDK];
__device__ __align__(16) __nv_bfloat16 g_X2h[(size_t)MTOT*LDK];
__device__ __align__(16) __nv_bfloat16 g_X2l[(size_t)MTOT*LDK];
__device__ __align__(16) __nv_bfloat16 g_W0h[NCH*LDK];
__device__ __align__(16) __nv_bfloat16 g_W0l[NCH*LDK];
__device__ __align__(16) __nv_bfloat16 g_W1h[NCH*LDK];
__device__ __align__(16) __nv_bfloat16 g_W1l[NCH*LDK];
__device__ __align__(16) __nv_bfloat16 g_W2h[NCH*LDK];
__device__ __align__(16) __nv_bfloat16 g_W2l[NCH*LDK];

// single dynamic-smem symbol for the whole TU (gemm only)
extern __shared__ char dynsm[];

// ---------------- helpers -----------------------------------------------------
__device__ __forceinline__ void cp16(uint32_t dst, const void* src){
    asm volatile("cp.async.cg.shared.global [%0], [%1], 16;" :: "r"(dst), "l"(src));
}
__device__ __forceinline__ void cp_commit(){
    asm volatile("cp.async.commit_group;");
}
template<int N> __device__ __forceinline__ void cp_wait(){
    asm volatile("cp.async.wait_group %0;" :: "n"(N));
}
__device__ __forceinline__ void ldm_x4(uint32_t* r, uint32_t addr){
    asm volatile("ldmatrix.sync.aligned.m8n8.x4.shared.b16 {%0,%1,%2,%3}, [%4];"
        : "=r"(r[0]), "=r"(r[1]), "=r"(r[2]), "=r"(r[3]) : "r"(addr));
}
__device__ __forceinline__ void mma_bf16(float* c, const uint32_t* a,
                                         uint32_t b0, uint32_t b1){
    asm volatile("mma.sync.aligned.m16n8k16.row.col.f32.bf16.bf16.f32 "
        "{%0,%1,%2,%3}, {%4,%5,%6,%7}, {%8,%9}, {%0,%1,%2,%3};"
        : "+f"(c[0]), "+f"(c[1]), "+f"(c[2]), "+f"(c[3])
        : "r"(a[0]), "r"(a[1]), "r"(a[2]), "r"(a[3]), "r"(b0), "r"(b1));
}
__device__ __forceinline__ void split_hl(float v, __nv_bfloat16& h, __nv_bfloat16& l){
    h = __float2bfloat16(v);
    l = __float2bfloat16(v - __bfloat162float(h));
}

// ---------------- FPS: 8-CTA cluster per batch, DSMEM mailbox (R12-proven) ----
__global__ void __launch_bounds__(FTHR,1) __cluster_dims__(FCNB,1,1)
fps_kernel(const float* __restrict__ xyz, float* __restrict__ o_xyz,
           float* __restrict__ o_inds)
{
    int bb  = blockIdx.x;          // 0..127
    int b   = bb >> 3;             // batch  (cluster id)
    int blk = bb & (FCNB-1);       // rank within cluster
    int t   = threadIdx.x;
    int wid = t >> 5, lane = t & 31;

    __shared__ __align__(16) float s_mb[2][4];   // mailbox: v,x,y,z per parity
    __shared__ int   s_mbi[2];
    __shared__ float s_v[8], s_x[8], s_y[8], s_z[8];
    __shared__ int   s_i[8];
    __shared__ float s_wx, s_wy, s_wz;
    __shared__ int   s_wi;

    uint32_t mb_a  = (uint32_t)__cvta_generic_to_shared(&s_mb[0][0]);
    uint32_t mbi_a = (uint32_t)__cvta_generic_to_shared(&s_mbi[0]);

    const float* base = xyz + (size_t)b*NPTS*3;
    int p0 = blk*(NPTS/FCNB) + t*FPPT;

    float px[FPPT], py[FPPT], pz[FPPT], dist[FPPT];
    #pragma unroll
    for (int i = 0; i < FPPT; i++) {
        px[i] = base[3*(p0+i)]; py[i] = base[3*(p0+i)+1]; pz[i] = base[3*(p0+i)+2];
        dist[i] = 1e10f;
    }

    float cx = base[0], cy = base[1], cz = base[2];
    int curi = 0;

    for (int k = 0; k < NS; k++) {
        if (blk == 0 && t == 0) {
            o_inds[b*NS + k] = (float)curi;
            o_xyz[(b*NS + k)*3 + 0] = cx;
            o_xyz[(b*NS + k)*3 + 1] = cy;
            o_xyz[(b*NS + k)*3 + 2] = cz;
        }
        float bv = -1.0f, bx = 0.f, by = 0.f, bz = 0.f; int bi = 0x3FFFFFFF;
        #pragma unroll
        for (int i = 0; i < FPPT; i++) {
            float dx = px[i]-cx, dy = py[i]-cy, dz = pz[i]-cz;
            // exact XLA order: (dx*dx + dy*dy) + dz*dz, no fma contraction
            float d = __fadd_rn(__fadd_rn(__fmul_rn(dx,dx),__fmul_rn(dy,dy)),
                                __fmul_rn(dz,dz));
            float nd = fminf(dist[i], d);
            dist[i] = nd;
            if (nd > bv) { bv = nd; bi = p0+i; bx = px[i]; by = py[i]; bz = pz[i]; }
        }
        // warp reduce (val,idx,x,y,z), tie -> lower idx
        #pragma unroll
        for (int o = 16; o > 0; o >>= 1) {
            float ov = __shfl_down_sync(0xffffffffu, bv, o);
            int   oi = __shfl_down_sync(0xffffffffu, bi, o);
            float ox = __shfl_down_sync(0xffffffffu, bx, o);
            float oy = __shfl_down_sync(0xffffffffu, by, o);
            float oz = __shfl_down_sync(0xffffffffu, bz, o);
            if (ov > bv || (ov == bv && oi < bi)) { bv=ov; bi=oi; bx=ox; by=oy; bz=oz; }
        }
        if (lane == 0) { s_v[wid]=bv; s_i[wid]=bi; s_x[wid]=bx; s_y[wid]=by; s_z[wid]=bz; }
        __syncthreads();

        int par = k & 1;
        if (wid == 0) {
            bv = (lane < 8) ? s_v[lane] : -1.0f;
            bi = (lane < 8) ? s_i[lane] : 0x3FFFFFFF;
            bx = (lane < 8) ? s_x[lane] : 0.f;
            by = (lane < 8) ? s_y[lane] : 0.f;
            bz = (lane < 8) ? s_z[lane] : 0.f;
            #pragma unroll
            for (int o = 4; o > 0; o >>= 1) {
                float ov = __shfl_down_sync(0xffffffffu, bv, o);
                int   oi = __shfl_down_sync(0xffffffffu, bi, o);
                float ox = __shfl_down_sync(0xffffffffu, bx, o);
                float oy = __shfl_down_sync(0xffffffffu, by, o);
                float oz = __shfl_down_sync(0xffffffffu, bz, o);
                if (ov > bv || (ov == bv && oi < bi)) { bv=ov; bi=oi; bx=ox; by=oy; bz=oz; }
            }
            if (lane == 0) {
                s_mb[par][0]=bv; s_mb[par][1]=bx; s_mb[par][2]=by; s_mb[par][3]=bz;
                s_mbi[par]=bi;
            }
        }
        // cluster barrier: arrive(release) orders the mailbox store; wait = acquire
        asm volatile("barrier.cluster.arrive.aligned;" ::: "memory");
        asm volatile("barrier.cluster.wait.aligned;" ::: "memory");

        if (wid == 0) {
            float vj = -1.0f, xj = 0.f, yj = 0.f, zj = 0.f; int ij = 0x3FFFFFFF;
            if (lane < FCNB) {
                uint32_t pa, pai;
                asm("mapa.shared::cluster.u32 %0, %1, %2;"
                    : "=r"(pa) : "r"(mb_a + (uint32_t)par*16), "r"(lane));
                asm("mapa.shared::cluster.u32 %0, %1, %2;"
                    : "=r"(pai) : "r"(mbi_a + (uint32_t)par*4), "r"(lane));
                asm volatile("ld.shared::cluster.v4.f32 {%0,%1,%2,%3}, [%4];"
                    : "=f"(vj), "=f"(xj), "=f"(yj), "=f"(zj) : "r"(pa));
                asm volatile("ld.shared::cluster.s32 %0, [%1];"
                    : "=r"(ij) : "r"(pai));
            }
            #pragma unroll
            for (int o = 4; o > 0; o >>= 1) {
                float ov = __shfl_down_sync(0xffffffffu, vj, o);
                int   oi = __shfl_down_sync(0xffffffffu, ij, o);
                float ox = __shfl_down_sync(0xffffffffu, xj, o);
                float oy = __shfl_down_sync(0xffffffffu, yj, o);
                float oz = __shfl_down_sync(0xffffffffu, zj, o);
                if (ov > vj || (ov == vj && oi < ij)) { vj=ov; ij=oi; xj=ox; yj=oy; zj=oz; }
            }
            if (lane == 0) { s_wx = xj; s_wy = yj; s_wz = zj; s_wi = ij; }
        }
        __syncthreads();
        cx = s_wx; cy = s_wy; cz = s_wz; curi = s_wi;
    }
    // no CTA may exit while peers' DSMEM reads of its smem are in flight
    asm volatile("barrier.cluster.arrive.aligned;" ::: "memory");
    asm volatile("barrier.cluster.wait.aligned;" ::: "memory");
}

// ---------------- ball query: one warp per center ----------------------------
__global__ void ball_kernel(const float* __restrict__ xyz,
                            const float* __restrict__ nxyz,
                            int* __restrict__ bidx)
{
    int gw = (blockIdx.x*blockDim.x + threadIdx.x) >> 5;
    int lane = threadIdx.x & 31;
    if (gw >= NB*NS) return;
    int b = gw >> 8;
    const float* px = xyz + (size_t)b*NPTS*3;
    float cx = nxyz[gw*3], cy = nxyz[gw*3+1], cz = nxyz[gw*3+2];
    int cnt = 0, first = -1;
    for (int n0 = 0; n0 < NPTS; n0 += 32) {
        int n = n0 + lane;
        float dx = px[3*n]-cx, dy = px[3*n+1]-cy, dz = px[3*n+2]-cz;
        float d2 = __fadd_rn(__fadd_rn(__fmul_rn(dx,dx),__fmul_rn(dy,dy)),
                             __fmul_rn(dz,dz));
        bool in = d2 < R2;
        unsigned m = __ballot_sync(0xffffffffu, in);
        if (first < 0 && m) first = n0 + __ffs(m) - 1;
        int pos = cnt + __popc(m & ((1u << lane) - 1u));
        if (in && pos < NKS) bidx[gw*NKS + pos] = n;
        cnt += __popc(m);
        if (cnt >= NKS) break;
    }
    int c = cnt < NKS ? cnt : NKS;
    for (int p = c + lane; p < NKS; p += 32) bidx[gw*NKS + p] = first;
}

// ---------------- gather (features + fp32 xyz rows) + W pack ------------------
// blocks [0, 4096): gather;  blocks [4096, 4096+3*NCH): weight pack rows
__global__ void __launch_bounds__(288)
gatherpack_kernel(const float* __restrict__ xyz,
                  const float* __restrict__ feat,
                  const float* __restrict__ nxyz,
                  const int* __restrict__ bidx,
                  __nv_bfloat16* __restrict__ Xh, __nv_bfloat16* __restrict__ Xl,
                  float* __restrict__ xyzr,
                  const float* __restrict__ W0, const float* __restrict__ W1,
                  const float* __restrict__ W2,
                  __nv_bfloat16* __restrict__ W0h, __nv_bfloat16* __restrict__ W0l,
                  __nv_bfloat16* __restrict__ W1h, __nv_bfloat16* __restrict__ W1l,
                  __nv_bfloat16* __restrict__ W2h, __nv_bfloat16* __restrict__ W2l)
{
    int w = blockIdx.x;
    int t = threadIdx.x;

    if (w >= NB*NS) {
        int r = w - NB*NS;                 // 0 .. 3*NCH-1
        int L = r / NCH, o = r % NCH;
        __nv_bfloat16 h, l;
        if (L == 0)      split_hl(W0[o*291 + 3 + t], h, l);   // feature cols only
        else if (L == 1) split_hl(W1[o*288 + t], h, l);
        else             split_hl(W2[o*288 + t], h, l);
        __nv_bfloat16* Wh = (L == 0) ? W0h : (L == 1) ? W1h : W2h;
        __nv_bfloat16* Wl = (L == 0) ? W0l : (L == 1) ? W1l : W2l;
        Wh[o*LDK + t] = h; Wl[o*LDK + t] = l;
        return;
    }

    int b = w >> 8;
    int n[NKS];
    #pragma unroll
    for (int j = 0; j < NKS; j++) n[j] = bidx[w*NKS + j];

    const float* frow = feat + (size_t)(b*NCH + t)*NPTS;
    #pragma unroll
    for (int j = 0; j < NKS; j++) {
        size_t row = (size_t)(w*NKS + j);
        __nv_bfloat16 h, l;
        split_hl(frow[n[j]], h, l);
        Xh[row*LDK + t] = h; Xl[row*LDK + t] = l;
        if (t < 3) {
            float p = xyz[((size_t)b*NPTS + n[j])*3 + t];
            float c = nxyz[w*3 + t];
            xyzr[row*3 + t] = __fdiv_rn(p - c, 0.3f);
        }
    }
}

// ---------------- mma.sync bf16-split GEMM + BN + ReLU (+xyz / +maxpool) ------
// CTA tile 128(M) x 96(N), K-chunk 32 (NC=9), 3-stage cp.async (2 CTAs/SM)
// single barrier per chunk: wait -> sync -> prefetch c+2 -> compute c
#define A_PL 8192               /* 128 rows * 64B */
#define B_PL 6144               /* 96 rows * 64B */
#define STG  (2*A_PL + 2*B_PL)  /* 28672 */
#define NSTG 3
#define NC   9

template<int MODE, int XYZ>   // MODE 0: write hi/lo planes of next X   1: fused maxpool
__global__ void __launch_bounds__(256,2)
gemm_mma(const __nv_bfloat16* __restrict__ Ah_g, const __nv_bfloat16* __restrict__ Al_g,
         const __nv_bfloat16* __restrict__ Wh_g, const __nv_bfloat16* __restrict__ Wl_g,
         const float* __restrict__ gg, const float* __restrict__ bb,
         const float* __restrict__ mmn, const float* __restrict__ vv,
         const float* __restrict__ w0raw, const float* __restrict__ xyzr,
         __nv_bfloat16* __restrict__ Xh_n, __nv_bfloat16* __restrict__ Xl_n,
         float* __restrict__ ofeat)
{
    __shared__ float s_sc[96], s_mu[96], s_be[96];
    __shared__ float s_w3[96*3];
    char* sm = dynsm;
    uint32_t smb = (uint32_t)__cvta_generic_to_shared(sm);

    int tid = threadIdx.x, lane = tid & 31, warp = tid >> 5;
    int brow = blockIdx.x * 128;
    int bcol = blockIdx.y * 96;
    int m_base = (warp >> 1) * 32;
    int n_base = (warp & 1) * 48;

    auto stage_load = [&](int c, int buf){
        int kc = c * 32;
        uint32_t sb = smb + buf*STG;
        #pragma unroll
        for (int i = 0; i < 4; i++) {
            int idx = tid + i*256;
            int plane = idx >> 9, rem = idx & 511;
            int r = rem >> 2, ch = rem & 3;
            uint32_t d = sb + plane*A_PL + r*64 + ((ch ^ (r & 3)) << 4);
            size_t gs = (size_t)(brow + r)*LDK + kc + ch*8;
            cp16(d, (plane ? Al_g : Ah_g) + gs);
        }
        #pragma unroll
        for (int i = 0; i < 3; i++) {
            int idx = tid + i*256;
            int plane = (idx >= 384), rem = plane ? idx - 384 : idx;
            int r = rem >> 2, ch = rem & 3;
            uint32_t d = sb + 2*A_PL + plane*B_PL + r*64 + ((ch ^ (r & 3)) << 4);
            size_t gs = (size_t)(bcol + r)*LDK + kc + ch*8;
            cp16(d, (plane ? Wl_g : Wh_g) + gs);
        }
    };

    stage_load(0, 0); cp_commit();
    stage_load(1, 1); cp_commit();

    for (int t = tid; t < 96; t += 256) {
        int gc = bcol + t;
        s_sc[t] = gg[gc] * rsqrtf(vv[gc] + 1e-5f);
        s_mu[t] = mmn[gc]; s_be[t] = bb[gc];
    }
    if (XYZ) {
        for (int u = tid; u < 288; u += 256) {
            int cc = u / 3, c = u % 3;
            s_w3[u] = w0raw[(size_t)(bcol + cc)*291 + c];
        }
    }

    float C[2][6][4];
    #pragma unroll
    for (int tm = 0; tm < 2; tm++)
        #pragma unroll
        for (int j = 0; j < 6; j++)
            #pragma unroll
            for (int e = 0; e < 4; e++) C[tm][j][e] = 0.f;

    int rA = (lane & 7) + ((lane & 8) ? 8 : 0);
    int chSelA = lane >> 4;
    int rB = (lane & 7) + ((lane & 16) ? 8 : 0);
    int chSelB = (lane >> 3) & 1;

    for (int c = 0; c < NC; c++) {
        int buf = c % NSTG;
        if (c + 1 < NC) cp_wait<1>(); else cp_wait<0>();
        __syncthreads();
        if (c + 2 < NC) { stage_load(c + 2, (c + 2) % NSTG); cp_commit(); }

        uint32_t sb = smb + buf*STG;
        uint32_t aH = sb, aL = sb + A_PL;
        uint32_t bH = sb + 2*A_PL, bL = bH + B_PL;

        #pragma unroll
        for (int ks = 0; ks < 2; ks++) {
            uint32_t ah[2][4], al[2][4];
            #pragma unroll
            for (int tm = 0; tm < 2; tm++) {
                int r = m_base + tm*16 + rA;
                int ch = ks*2 + chSelA;
                uint32_t off = r*64 + ((ch ^ (r & 3)) << 4);
                ldm_x4(ah[tm], aH + off);
                ldm_x4(al[tm], aL + off);
            }
            uint32_t bh[3][4], bl[3][4];
            #pragma unroll
            for (int jp = 0; jp < 3; jp++) {
                int r = n_base + jp*16 + rB;
                int ch = ks*2 + chSelB;
                uint32_t off = r*64 + ((ch ^ (r & 3)) << 4);
                ldm_x4(bh[jp], bH + off);
                ldm_x4(bl[jp], bL + off);
            }
            #pragma unroll
            for (int tm = 0; tm < 2; tm++)
                #pragma unroll
                for (int jp = 0; jp < 3; jp++) {
                    mma_bf16(C[tm][2*jp],   ah[tm], bh[jp][0], bh[jp][1]);
                    mma_bf16(C[tm][2*jp],   ah[tm], bl[jp][0], bl[jp][1]);
                    mma_bf16(C[tm][2*jp],   al[tm], bh[jp][0], bh[jp][1]);
                    mma_bf16(C[tm][2*jp+1], ah[tm], bh[jp][2], bh[jp][3]);
                    mma_bf16(C[tm][2*jp+1], ah[tm], bl[jp][2], bl[jp][3]);
                    mma_bf16(C[tm][2*jp+1], al[tm], bh[jp][2], bh[jp][3]);
                }
        }
    }

    // ---------------- epilogue ----------------
    int tq = lane >> 2, tr = lane & 3;
    float xr[4][3];
    if (XYZ) {
        #pragma unroll
        for (int q = 0; q < 4; q++) {
            int rr = brow + m_base + (q >> 1)*16 + (q & 1)*8 + tq;
            xr[q][0] = xyzr[(size_t)rr*3 + 0];
            xr[q][1] = xyzr[(size_t)rr*3 + 1];
            xr[q][2] = xyzr[(size_t)rr*3 + 2];
        }
    }
    #pragma unroll
    for (int tm = 0; tm < 2; tm++) {
        #pragma unroll
        for (int j = 0; j < 6; j++) {
            int lc = n_base + j*8 + tr*2;
            int col = bcol + lc;
            float c0 = C[tm][j][0], c1 = C[tm][j][1];
            float c2 = C[tm][j][2], c3 = C[tm][j][3];
            if (XYZ) {
                const float* wa = &s_w3[lc*3];
                const float* wb = &s_w3[(lc+1)*3];
                int qa = tm*2, qb = tm*2 + 1;
                c0 += xr[qa][0]*wa[0] + xr[qa][1]*wa[1] + xr[qa][2]*wa[2];
                c1 += xr[qa][0]*wb[0] + xr[qa][1]*wb[1] + xr[qa][2]*wb[2];
                c2 += xr[qb][0]*wa[0] + xr[qb][1]*wa[1] + xr[qb][2]*wa[2];
                c3 += xr[qb][0]*wb[0] + xr[qb][1]*wb[1] + xr[qb][2]*wb[2];
            }
            float y0 = fmaxf(__fmaf_rn(c0 - s_mu[lc],   s_sc[lc],   s_be[lc]),   0.f);
            float y1 = fmaxf(__fmaf_rn(c1 - s_mu[lc+1], s_sc[lc+1], s_be[lc+1]), 0.f);
            float y2 = fmaxf(__fmaf_rn(c2 - s_mu[lc],   s_sc[lc],   s_be[lc]),   0.f);
            float y3 = fmaxf(__fmaf_rn(c3 - s_mu[lc+1], s_sc[lc+1], s_be[lc+1]), 0.f);

            if (MODE == 0) {
                size_t r0 = (size_t)(brow + m_base + tm*16 + tq)*LDK + col;
                size_t r1 = r0 + 8*LDK;
                __nv_bfloat16 h0,l0,h1,l1;
                split_hl(y0,h0,l0); split_hl(y1,h1,l1);
                *(__nv_bfloat162*)(Xh_n + r0) = __nv_bfloat162(h0,h1);
                *(__nv_bfloat162*)(Xl_n + r0) = __nv_bfloat162(l0,l1);
                split_hl(y2,h0,l0); split_hl(y3,h1,l1);
                *(__nv_bfloat162*)(Xh_n + r1) = __nv_bfloat162(h0,h1);
                *(__nv_bfloat162*)(Xl_n + r1) = __nv_bfloat162(l0,l1);
            } else {
                float m0 = fmaxf(y0, y2), m1 = fmaxf(y1, y3);
                #pragma unroll
                for (int o = 4; o <= 16; o <<= 1) {
                    m0 = fmaxf(m0, __shfl_xor_sync(0xffffffffu, m0, o));
                    m1 = fmaxf(m1, __shfl_xor_sync(0xffffffffu, m1, o));
                }
                if (tq == 0) {
                    int center = (brow + m_base + tm*16) >> 4;
                    int b = center >> 8, s = center & 255;
                    ofeat[((size_t)b*NCH + col)*NS + s]     = m0;
                    ofeat[((size_t)b*NCH + col+1)*NS + s]   = m1;
                }
            }
        }
    }
}

// ---------------- launch ------------------------------------------------------
extern "C" void kernel_launch(void* const* d_in, const int* in_sizes, int n_in,
                              void* d_out, int out_size)
{
    const float* xyz  = (const float*)d_in[0];
    const float* feat = (const float*)d_in[1];
    const float* W0 = (const float*)d_in[2];
    const float* g0 = (const float*)d_in[3];
    const float* b0 = (const float*)d_in[4];
    const float* m0 = (const float*)d_in[5];
    const float* v0 = (const float*)d_in[6];
    const float* W1 = (const float*)d_in[7];
    const float* g1 = (const float*)d_in[8];
    const float* b1 = (const float*)d_in[9];
    const float* m1 = (const float*)d_in[10];
    const float* v1 = (const float*)d_in[11];
    const float* W2 = (const float*)d_in[12];
    const float* g2 = (const float*)d_in[13];
    const float* b2 = (const float*)d_in[14];
    const float* m2 = (const float*)d_in[15];
    const float* v2 = (const float*)d_in[16];

    float* out    = (float*)d_out;
    float* o_xyz  = out;
    float* o_feat = out + (size_t)NB*NS*3;
    float* o_inds = o_feat + (size_t)NB*NCH*NS;

    void *pX0h,*pX0l,*pX1h,*pX1l,*pX2h,*pX2l,*pW0h,*pW0l,*pW1h,*pW1l,*pW2h,*pW2l,*pBI,*pXR;
    cudaGetSymbolAddress(&pX0h, g_X0h); cudaGetSymbolAddress(&pX0l, g_X0l);
    cudaGetSymbolAddress(&pX1h, g_X1h); cudaGetSymbolAddress(&pX1l, g_X1l);
    cudaGetSymbolAddress(&pX2h, g_X2h); cudaGetSymbolAddress(&pX2l, g_X2l);
    cudaGetSymbolAddress(&pW0h, g_W0h); cudaGetSymbolAddress(&pW0l, g_W0l);
    cudaGetSymbolAddress(&pW1h, g_W1h); cudaGetSymbolAddress(&pW1l, g_W1l);
    cudaGetSymbolAddress(&pW2h, g_W2h); cudaGetSymbolAddress(&pW2l, g_W2l);
    cudaGetSymbolAddress(&pBI, g_ballidx);
    cudaGetSymbolAddress(&pXR, g_xyzr);

    cudaFuncSetAttribute((gemm_mma<0,1>),
        cudaFuncAttributeMaxDynamicSharedMemorySize, NSTG*STG);
    cudaFuncSetAttribute((gemm_mma<0,0>),
        cudaFuncAttributeMaxDynamicSharedMemorySize, NSTG*STG);
    cudaFuncSetAttribute((gemm_mma<1,0>),
        cudaFuncAttributeMaxDynamicSharedMemorySize, NSTG*STG);

    fps_kernel<<<NB*FCNB, FTHR>>>(xyz, o_xyz, o_inds);
    ball_kernel<<<(NB*NS)/4, 128>>>(xyz, o_xyz, (int*)pBI);
    gatherpack_kernel<<<NB*NS + 3*NCH, NCH>>>(xyz, feat, o_xyz, (const int*)pBI,
        (__nv_bfloat16*)pX0h, (__nv_bfloat16*)pX0l, (float*)pXR,
        W0, W1, W2,
        (__nv_bfloat16*)pW0h, (__nv_bfloat16*)pW0l,
        (__nv_bfloat16*)pW1h, (__nv_bfloat16*)pW1l,
        (__nv_bfloat16*)pW2h, (__nv_bfloat16*)pW2l);

    dim3 gdim(MTOT/128, 3);
    gemm_mma<0,1><<<gdim, 256, NSTG*STG>>>(
        (const __nv_bfloat16*)pX0h, (const __nv_bfloat16*)pX0l,
        (const __nv_bfloat16*)pW0h, (const __nv_bfloat16*)pW0l,
        g0, b0, m0, v0, W0, (const float*)pXR,
        (__nv_bfloat16*)pX1h, (__nv_bfloat16*)pX1l, nullptr);
    gemm_mma<0,0><<<gdim, 256, NSTG*STG>>>(
        (const __nv_bfloat16*)pX1h, (const __nv_bfloat16*)pX1l,
        (const __nv_bfloat16*)pW1h, (const __nv_bfloat16*)pW1l,
        g1, b1, m1, v1, nullptr, nullptr,
        (__nv_bfloat16*)pX2h, (__nv_bfloat16*)pX2l, nullptr);
    gemm_mma<1,0><<<gdim, 256, NSTG*STG>>>(
        (const __nv_bfloat16*)pX2h, (const __nv_bfloat16*)pX2l,
        (const __nv_bfloat16*)pW2h, (const __nv_bfloat16*)pW2l,
        g2, b2, m2, v2, nullptr, nullptr,
        nullptr, nullptr, o_feat);
}